// round 12
// baseline (speedup 1.0000x reference)
#include <cuda_runtime.h>
#include <cuda_bf16.h>
#include <cstdint>

#define B_SZ   2048
#define N_INST 8
#define N_FEAT 100
#define N_HID  40
#define NC     40
#define NM     41
#define NTHR   256
#define BT     64

#define IMGA_C 17920              // 7 kstep x 5 ntile x 32 thr x 16B
#define IMGB_C 19968              // 3 kstep x 13 ntile x 32 thr x 16B
#define SLOT   19968              // 1-c ring slot (max of the two)

// smem layout: 2 groups x 2 slots, then tiles
#define SM_RING 0                 // 2*2*19968 = 79872
#define SM_MSK  79872             // [40][64] f32 = 10240
#define SM_HP   90112             // 2 x [64][40] f32 = 20480
#define SM_BIAS 110592            // 512
#define SM_TOTAL 111104           // x2 CTAs = 222208 <= 228KB/SM

__device__ __align__(16) unsigned char g_imgA[N_INST * NC * IMGA_C];
__device__ __align__(16) unsigned char g_imgB[N_INST * NC * IMGB_C];

// ===================== helpers =====================
__device__ __forceinline__ uint32_t smem_u32(const void* p) {
    return (uint32_t)__cvta_generic_to_shared(p);
}
__device__ __forceinline__ void cp16(uint32_t d, const void* s) {
    asm volatile("cp.async.cg.shared.global [%0], [%1], 16;" :: "r"(d), "l"(s) : "memory");
}
#define CP_COMMIT() asm volatile("cp.async.commit_group;" ::: "memory")
#define CP_WAIT0()  asm volatile("cp.async.wait_group 0;" ::: "memory")
// group-local stage: 128 threads
__device__ __forceinline__ void stageG(uint32_t dst, const unsigned char* src, int bytes, int tg) {
    for (int o = tg * 16; o < bytes; o += 128 * 16) cp16(dst + o, src + o);
}
#define BARG(id) asm volatile("bar.sync %0, 128;" :: "r"(id) : "memory")

__device__ __forceinline__ void mma_bf16(float* d, const uint32_t* a, uint32_t b0, uint32_t b1) {
    asm volatile("mma.sync.aligned.m16n8k16.row.col.f32.bf16.bf16.f32 "
                 "{%0,%1,%2,%3},{%4,%5,%6,%7},{%8,%9},{%0,%1,%2,%3};"
                 : "+f"(d[0]), "+f"(d[1]), "+f"(d[2]), "+f"(d[3])
                 : "r"(a[0]), "r"(a[1]), "r"(a[2]), "r"(a[3]), "r"(b0), "r"(b1));
}
__device__ __forceinline__ void mma_bf16_k8(float* d, uint32_t a0, uint32_t a1, uint32_t b0) {
    asm volatile("mma.sync.aligned.m16n8k8.row.col.f32.bf16.bf16.f32 "
                 "{%0,%1,%2,%3},{%4,%5},{%6},{%0,%1,%2,%3};"
                 : "+f"(d[0]), "+f"(d[1]), "+f"(d[2]), "+f"(d[3])
                 : "r"(a0), "r"(a1), "r"(b0));
}
__device__ __forceinline__ uint32_t pack_bf2(float a, float b) {
    __nv_bfloat162 t = __floats2bfloat162_rn(a, b);
    return *reinterpret_cast<uint32_t*>(&t);
}
__device__ __forceinline__ void split_pair(float a, float b, uint32_t& hi, uint32_t& lo) {
    const __nv_bfloat16 ah = __float2bfloat16(a), bh = __float2bfloat16(b);
    hi = pack_bf2(a, b);
    lo = pack_bf2(a - __bfloat162float(ah), b - __bfloat162float(bh));
}
__device__ __forceinline__ uint4 frag_word(float v00, float v01, float v10, float v11) {
    uint4 w; uint32_t h0, l0, h1, l1;
    split_pair(v00, v01, h0, l0);
    split_pair(v10, v11, h1, l1);
    w.x = h0; w.y = h1; w.z = l0; w.w = l1;
    return w;
}

// ===================== Kernel 1: G -> fragment images =====================
__global__ __launch_bounds__(256)
void compute_G_kernel(const float* __restrict__ A, const float* __restrict__ Bp) {
    __shared__ float AsT[NM * N_FEAT];
    __shared__ float Bs[NM * N_HID];
    __shared__ float sS[N_FEAT * N_HID];
    const int ic = blockIdx.x;
    const float* Ap  = A  + (size_t)ic * N_FEAT * NM;
    const float* Bpp = Bp + (size_t)ic * NM * N_HID;
    uint4* iA = reinterpret_cast<uint4*>(g_imgA + (size_t)ic * IMGA_C);
    uint4* iB = reinterpret_cast<uint4*>(g_imgB + (size_t)ic * IMGB_C);

    for (int idx = threadIdx.x; idx < N_FEAT * NM; idx += blockDim.x) {
        const int f = idx / NM, m = idx % NM;
        AsT[m * N_FEAT + f] = Ap[idx];
    }
    for (int idx = threadIdx.x; idx < NM * N_HID; idx += blockDim.x) Bs[idx] = Bpp[idx];
    __syncthreads();

    for (int t = threadIdx.x; t < 1000; t += blockDim.x) {
        const int fp = t / 20, hp = t % 20;
        float a00 = 0.f, a01 = 0.f, a10 = 0.f, a11 = 0.f;
#pragma unroll
        for (int m = 0; m < NM; m++) {
            const float2 a = *reinterpret_cast<const float2*>(&AsT[m * N_FEAT + fp * 2]);
            const float2 b = *reinterpret_cast<const float2*>(&Bs[m * N_HID + hp * 2]);
            a00 = fmaf(a.x, b.x, a00); a01 = fmaf(a.x, b.y, a01);
            a10 = fmaf(a.y, b.x, a10); a11 = fmaf(a.y, b.y, a11);
        }
        *reinterpret_cast<float2*>(&sS[(fp * 2)     * N_HID + hp * 2]) = make_float2(a00, a01);
        *reinterpret_cast<float2*>(&sS[(fp * 2 + 1) * N_HID + hp * 2]) = make_float2(a10, a11);
    }
    __syncthreads();

    for (int widx = threadIdx.x; widx < 7 * 5 * 32; widx += blockDim.x) {
        const int kst = widx / 160, rem = widx % 160;
        const int nt = rem / 32, T = rem % 32;
        const int q = T & 3, tr = T >> 2;
        const int n = nt * 8 + tr;
        float v[2][2];
#pragma unroll
        for (int half = 0; half < 2; half++)
#pragma unroll
            for (int lo = 0; lo < 2; lo++) {
                const int f = kst * 16 + q * 2 + half * 8 + lo;
                v[half][lo] = (f < N_FEAT) ? sS[f * N_HID + n] : 0.f;
            }
        iA[widx] = frag_word(v[0][0], v[0][1], v[1][0], v[1][1]);
    }
    for (int widx = threadIdx.x; widx < 3 * 13 * 32; widx += blockDim.x) {
        const int kst = widx / 416, rem = widx % 416;
        const int nt = rem / 32, T = rem % 32;
        const int q = T & 3, tr = T >> 2;
        const int f = nt * 8 + tr;
        float v[2][2];
#pragma unroll
        for (int half = 0; half < 2; half++)
#pragma unroll
            for (int lo = 0; lo < 2; lo++) {
                const int h = kst * 16 + q * 2 + half * 8 + lo;
                v[half][lo] = (f < N_FEAT && h < N_HID) ? sS[f * N_HID + h] : 0.f;
            }
        iB[widx] = frag_word(v[0][0], v[0][1], v[1][0], v[1][1]);
    }
}

// ===================== Kernel 2: 256 thr, BT=64, 2 CTAs/SM =====================
__global__ __launch_bounds__(NTHR, 2)
void tmsspd_main_kernel(const float* __restrict__ x, const float* __restrict__ mask,
                        const float* __restrict__ bfin, float* __restrict__ out) {
    extern __shared__ char smem[];
    float* mskS  = reinterpret_cast<float*>(smem + SM_MSK);
    float* hp0   = reinterpret_cast<float*>(smem + SM_HP);        // [64][40]
    float* hp1   = hp0 + BT * N_HID;
    float* biasS = reinterpret_cast<float*>(smem + SM_BIAS);

    const int i   = blockIdx.y;
    const int b0  = blockIdx.x * BT;
    const int tid = threadIdx.x;
    const int w   = tid >> 5;
    const int T   = tid & 31;
    const int g   = w >> 2;            // c-group: 0 -> c 0..19, 1 -> c 20..39
    const int tg  = tid & 127;
    const int wg  = w & 3;
    const int q   = T & 3;
    const int tr  = T >> 2;
    const int r0  = wg * 16 + tr;
    const int r1  = r0 + 8;
    const int barid = 1 + g;

    const uint32_t rb = smem_u32(smem) + SM_RING + (uint32_t)g * (2 * SLOT);
    const char* rbp = smem + SM_RING + g * (2 * SLOT);

    const unsigned char* imgAg = g_imgA + (size_t)(i * NC + g * 20) * IMGA_C;
    const unsigned char* imgBg = g_imgB + (size_t)(i * NC + g * 20) * IMGB_C;

    // prologue: stage this group's c0 into slot 0
    stageG(rb, imgAg, IMGA_C, tg); CP_COMMIT();

    for (int idx = tid; idx < BT * NC; idx += NTHR) {
        const int r = idx / NC, c = idx % NC;
        mskS[c * BT + r] = mask[((size_t)(b0 + r) * N_INST + i) * NC + c];
    }
    if (tid < N_FEAT) biasS[tid] = bfin[i * N_FEAT + tid];

    // X fragments: kst 0..5 full k16, kst6 k8 (f 96..103)
    uint32_t xhi[6][4], xlo[6][4], xh6[2], xl6[2];
    {
        const float* xr0 = x + ((size_t)(b0 + r0) * N_INST + i) * N_FEAT;
        const float* xr1 = x + ((size_t)(b0 + r1) * N_INST + i) * N_FEAT;
#pragma unroll
        for (int kst = 0; kst < 6; kst++) {
#pragma unroll
            for (int half = 0; half < 2; half++) {
                const int kk = kst * 16 + q * 2 + half * 8;
                const float2 v0 = *reinterpret_cast<const float2*>(xr0 + kk);
                const float2 v1 = *reinterpret_cast<const float2*>(xr1 + kk);
                split_pair(v0.x, v0.y, xhi[kst][half * 2],     xlo[kst][half * 2]);
                split_pair(v1.x, v1.y, xhi[kst][half * 2 + 1], xlo[kst][half * 2 + 1]);
            }
        }
        const int kk = 96 + q * 2;
        float2 v0 = make_float2(0.f, 0.f), v1 = make_float2(0.f, 0.f);
        if (kk < N_FEAT) {
            v0 = *reinterpret_cast<const float2*>(xr0 + kk);
            v1 = *reinterpret_cast<const float2*>(xr1 + kk);
        }
        split_pair(v0.x, v0.y, xh6[0], xl6[0]);
        split_pair(v1.x, v1.y, xh6[1], xl6[1]);
    }
    __syncthreads();   // mask/bias visible

    // ================= Phase A: 20 c-iterations per group, 1 barrier each =================
    float hacc[5][4];
#pragma unroll
    for (int nt = 0; nt < 5; nt++)
#pragma unroll
        for (int j = 0; j < 4; j++) hacc[nt][j] = 0.f;

    for (int k = 0; k < 20; k++) {
        CP_WAIT0();                 // my slices of slot k&1 (content c_k) done
        BARG(barid);                // all slices visible; all finished compute(k-1)
        if (k + 1 < 20) {           // slot (k+1)&1 freed by compute(k-1), proven by BARG
            stageG(rb + ((k + 1) & 1) * SLOT, imgAg + (size_t)(k + 1) * IMGA_C, IMGA_C, tg);
            CP_COMMIT();
        }
        const char* buf = rbp + (k & 1) * SLOT;
        const int c = g * 20 + k;
        float d[5][4];
#pragma unroll
        for (int nt = 0; nt < 5; nt++)
#pragma unroll
            for (int j = 0; j < 4; j++) d[nt][j] = 0.f;

#pragma unroll
        for (int kst = 0; kst < 6; kst++) {
            uint4 wv[5];
#pragma unroll
            for (int nt = 0; nt < 5; nt++)
                wv[nt] = *reinterpret_cast<const uint4*>(buf + (((kst * 5 + nt) * 32 + T) << 4));
#pragma unroll
            for (int nt = 0; nt < 5; nt++) mma_bf16(d[nt], xhi[kst], wv[nt].x, wv[nt].y);
#pragma unroll
            for (int nt = 0; nt < 5; nt++) mma_bf16(d[nt], xhi[kst], wv[nt].z, wv[nt].w);
#pragma unroll
            for (int nt = 0; nt < 5; nt++) mma_bf16(d[nt], xlo[kst], wv[nt].x, wv[nt].y);
        }
        {   // kst 6: k8
            uint4 wv[5];
#pragma unroll
            for (int nt = 0; nt < 5; nt++)
                wv[nt] = *reinterpret_cast<const uint4*>(buf + (((6 * 5 + nt) * 32 + T) << 4));
#pragma unroll
            for (int nt = 0; nt < 5; nt++) mma_bf16_k8(d[nt], xh6[0], xh6[1], wv[nt].x);
#pragma unroll
            for (int nt = 0; nt < 5; nt++) mma_bf16_k8(d[nt], xh6[0], xh6[1], wv[nt].z);
#pragma unroll
            for (int nt = 0; nt < 5; nt++) mma_bf16_k8(d[nt], xl6[0], xl6[1], wv[nt].x);
        }
        const float m0 = mskS[c * BT + r0];
        const float m1 = mskS[c * BT + r1];
#pragma unroll
        for (int nt = 0; nt < 5; nt++) {
            hacc[nt][0] = fmaf(m0, d[nt][0], hacc[nt][0]);
            hacc[nt][1] = fmaf(m0, d[nt][1], hacc[nt][1]);
            hacc[nt][2] = fmaf(m1, d[nt][2], hacc[nt][2]);
            hacc[nt][3] = fmaf(m1, d[nt][3], hacc[nt][3]);
        }
    }

    // group partial h
    {
        float* hp = g ? hp1 : hp0;
#pragma unroll
        for (int nt = 0; nt < 5; nt++) {
            const int col = nt * 8 + q * 2;
            *reinterpret_cast<float2*>(&hp[r0 * N_HID + col]) = make_float2(hacc[nt][0], hacc[nt][1]);
            *reinterpret_cast<float2*>(&hp[r1 * N_HID + col]) = make_float2(hacc[nt][2], hacc[nt][3]);
        }
    }
    // stage B c0 into slot0 (held A c18; BARG(19) proved compute(18) done group-wide)
    stageG(rb, imgBg, IMGB_C, tg); CP_COMMIT();
    __syncthreads();   // both partials visible

    // h fragments from summed partials: kst 0,1 k16; kst2 k8
    uint32_t hh[2][4], hl[2][4], hh2[2], hl2[2];
#pragma unroll
    for (int kst = 0; kst < 2; kst++) {
#pragma unroll
        for (int half = 0; half < 2; half++) {
            const int kk = kst * 16 + q * 2 + half * 8;
            const float2 a0 = *reinterpret_cast<const float2*>(&hp0[r0 * N_HID + kk]);
            const float2 b0v = *reinterpret_cast<const float2*>(&hp1[r0 * N_HID + kk]);
            const float2 a1 = *reinterpret_cast<const float2*>(&hp0[r1 * N_HID + kk]);
            const float2 b1v = *reinterpret_cast<const float2*>(&hp1[r1 * N_HID + kk]);
            split_pair(a0.x + b0v.x, a0.y + b0v.y, hh[kst][half * 2],     hl[kst][half * 2]);
            split_pair(a1.x + b1v.x, a1.y + b1v.y, hh[kst][half * 2 + 1], hl[kst][half * 2 + 1]);
        }
    }
    {
        const int kk = 32 + q * 2;
        const float2 a0 = *reinterpret_cast<const float2*>(&hp0[r0 * N_HID + kk]);
        const float2 b0v = *reinterpret_cast<const float2*>(&hp1[r0 * N_HID + kk]);
        const float2 a1 = *reinterpret_cast<const float2*>(&hp0[r1 * N_HID + kk]);
        const float2 b1v = *reinterpret_cast<const float2*>(&hp1[r1 * N_HID + kk]);
        split_pair(a0.x + b0v.x, a0.y + b0v.y, hh2[0], hl2[0]);
        split_pair(a1.x + b1v.x, a1.y + b1v.y, hh2[1], hl2[1]);
    }

    // ================= Phase B: 20 c-iterations per group =================
    float oacc[13][4];
#pragma unroll
    for (int nt = 0; nt < 13; nt++)
#pragma unroll
        for (int j = 0; j < 4; j++) oacc[nt][j] = 0.f;

    for (int k = 0; k < 20; k++) {
        CP_WAIT0();
        BARG(barid);
        if (k + 1 < 20) {
            stageG(rb + ((k + 1) & 1) * SLOT, imgBg + (size_t)(k + 1) * IMGB_C, IMGB_C, tg);
            CP_COMMIT();
        }
        const char* buf = rbp + (k & 1) * SLOT;
        const int c = g * 20 + k;
        const uint32_t keep0 = (mskS[c * BT + r0] != 0.f) ? 0xFFFFFFFFu : 0u;
        const uint32_t keep1 = (mskS[c * BT + r1] != 0.f) ? 0xFFFFFFFFu : 0u;

#pragma unroll
        for (int kst = 0; kst < 2; kst++) {
            uint32_t ah[4], al[4];
            ah[0] = hh[kst][0] & keep0; ah[1] = hh[kst][1] & keep1;
            ah[2] = hh[kst][2] & keep0; ah[3] = hh[kst][3] & keep1;
            al[0] = hl[kst][0] & keep0; al[1] = hl[kst][1] & keep1;
            al[2] = hl[kst][2] & keep0; al[3] = hl[kst][3] & keep1;
            {
                uint4 wv[7];
#pragma unroll
                for (int j = 0; j < 7; j++)
                    wv[j] = *reinterpret_cast<const uint4*>(buf + (((kst * 13 + j) * 32 + T) << 4));
#pragma unroll
                for (int j = 0; j < 7; j++) mma_bf16(oacc[j], ah, wv[j].x, wv[j].y);
#pragma unroll
                for (int j = 0; j < 7; j++) mma_bf16(oacc[j], ah, wv[j].z, wv[j].w);
#pragma unroll
                for (int j = 0; j < 7; j++) mma_bf16(oacc[j], al, wv[j].x, wv[j].y);
            }
            {
                uint4 wv[6];
#pragma unroll
                for (int j = 0; j < 6; j++)
                    wv[j] = *reinterpret_cast<const uint4*>(buf + (((kst * 13 + 7 + j) * 32 + T) << 4));
#pragma unroll
                for (int j = 0; j < 6; j++) mma_bf16(oacc[7 + j], ah, wv[j].x, wv[j].y);
#pragma unroll
                for (int j = 0; j < 6; j++) mma_bf16(oacc[7 + j], ah, wv[j].z, wv[j].w);
#pragma unroll
                for (int j = 0; j < 6; j++) mma_bf16(oacc[7 + j], al, wv[j].x, wv[j].y);
            }
        }
        {   // kst 2: k8
            const uint32_t a0 = hh2[0] & keep0, a1 = hh2[1] & keep1;
            const uint32_t c0 = hl2[0] & keep0, c1 = hl2[1] & keep1;
            {
                uint4 wv[7];
#pragma unroll
                for (int j = 0; j < 7; j++)
                    wv[j] = *reinterpret_cast<const uint4*>(buf + (((2 * 13 + j) * 32 + T) << 4));
#pragma unroll
                for (int j = 0; j < 7; j++) mma_bf16_k8(oacc[j], a0, a1, wv[j].x);
#pragma unroll
                for (int j = 0; j < 7; j++) mma_bf16_k8(oacc[j], a0, a1, wv[j].z);
#pragma unroll
                for (int j = 0; j < 7; j++) mma_bf16_k8(oacc[j], c0, c1, wv[j].x);
            }
            {
                uint4 wv[6];
#pragma unroll
                for (int j = 0; j < 6; j++)
                    wv[j] = *reinterpret_cast<const uint4*>(buf + (((2 * 13 + 7 + j) * 32 + T) << 4));
#pragma unroll
                for (int j = 0; j < 6; j++) mma_bf16_k8(oacc[7 + j], a0, a1, wv[j].x);
#pragma unroll
                for (int j = 0; j < 6; j++) mma_bf16_k8(oacc[7 + j], a0, a1, wv[j].z);
#pragma unroll
                for (int j = 0; j < 6; j++) mma_bf16_k8(oacc[7 + j], c0, c1, wv[j].x);
            }
        }
    }

    // ================= cross-group reduce + epilogue =================
    float* stash = reinterpret_cast<float*>(smem);   // [64][104], ring dead
    __syncthreads();
    if (g == 1) {
#pragma unroll
        for (int nt = 0; nt < 13; nt++) {
            const int col = nt * 8 + q * 2;
            *reinterpret_cast<float2*>(&stash[r0 * 104 + col]) = make_float2(oacc[nt][0], oacc[nt][1]);
            *reinterpret_cast<float2*>(&stash[r1 * 104 + col]) = make_float2(oacc[nt][2], oacc[nt][3]);
        }
    }
    __syncthreads();
    if (g == 0) {
        float* o0 = out + ((size_t)(b0 + r0) * N_INST + i) * N_FEAT;
        float* o1 = out + ((size_t)(b0 + r1) * N_INST + i) * N_FEAT;
#pragma unroll
        for (int nt = 0; nt < 13; nt++) {
            const int col = nt * 8 + q * 2;
            if (col < N_FEAT) {
                const float2 s0 = *reinterpret_cast<const float2*>(&stash[r0 * 104 + col]);
                const float2 s1 = *reinterpret_cast<const float2*>(&stash[r1 * 104 + col]);
                const float2 bf = *reinterpret_cast<const float2*>(&biasS[col]);
                float2 a, b;
                a.x = fmaxf(oacc[nt][0] + s0.x + bf.x, 0.f);
                a.y = fmaxf(oacc[nt][1] + s0.y + bf.y, 0.f);
                b.x = fmaxf(oacc[nt][2] + s1.x + bf.x, 0.f);
                b.y = fmaxf(oacc[nt][3] + s1.y + bf.y, 0.f);
                *reinterpret_cast<float2*>(o0 + col) = a;
                *reinterpret_cast<float2*>(o1 + col) = b;
            }
        }
    }
}

// ---------------------------------------------------------------------------
extern "C" void kernel_launch(void* const* d_in, const int* in_sizes, int n_in,
                              void* d_out, int out_size) {
    (void)in_sizes; (void)n_in; (void)out_size;
    const float* x    = (const float*)d_in[0];
    const float* mask = (const float*)d_in[1];
    const float* A    = (const float*)d_in[2];
    const float* Bp   = (const float*)d_in[3];
    const float* bfin = (const float*)d_in[4];
    float* out = (float*)d_out;

    cudaFuncSetAttribute(tmsspd_main_kernel,
                         cudaFuncAttributeMaxDynamicSharedMemorySize, SM_TOTAL);

    compute_G_kernel<<<N_INST * NC, 256>>>(A, Bp);

    dim3 grid(B_SZ / BT, N_INST);
    tmsspd_main_kernel<<<grid, NTHR, SM_TOTAL>>>(x, mask, bfin, out);
}

// round 13
// speedup vs baseline: 1.0560x; 1.0560x over previous
#include <cuda_runtime.h>
#include <cuda_bf16.h>
#include <cstdint>

#define B_SZ   2048
#define N_INST 8
#define N_FEAT 100
#define N_HID  40
#define NM     41
#define NC     40
#define NTHR   512

#define IMGA_C 17920
#define IMGB_C 19968
#define SLOTA  (2*IMGA_C)
#define SLOTB  (2*IMGB_C)
#define SLOT   39936               // ring slot (holds a 2-c pair)

#define SM_RING 0                  // 2 groups x 2 slots x 39936 = 159744
#define SM_MSK  159744             // [40][128] f32 = 20480
#define SM_HP   180224             // 2 x [128][40] f32 = 40960
#define SM_BIAS 221184             // 512
#define SM_MB   221696             // 4 mbarriers (u64)
#define SM_TOTAL 221760

__device__ __align__(16) unsigned char g_imgA[N_INST * NC * IMGA_C];
__device__ __align__(16) unsigned char g_imgB[N_INST * NC * IMGB_C];

// ===================== helpers =====================
__device__ __forceinline__ uint32_t smem_u32(const void* p) {
    return (uint32_t)__cvta_generic_to_shared(p);
}
#define BARG(id) asm volatile("bar.sync %0, 256;" :: "r"(id) : "memory")
__device__ __forceinline__ void mbar_init(uint32_t mb, uint32_t n) {
    asm volatile("mbarrier.init.shared.b64 [%0], %1;" :: "r"(mb), "r"(n) : "memory");
}
__device__ __forceinline__ void mbar_expect(uint32_t mb, uint32_t bytes) {
    asm volatile("mbarrier.arrive.expect_tx.shared.b64 _, [%0], %1;" :: "r"(mb), "r"(bytes) : "memory");
}
__device__ __forceinline__ void mbar_wait(uint32_t mb, uint32_t ph) {
    asm volatile("{\n\t.reg .pred P;\nW_%=:\n\t"
                 "mbarrier.try_wait.parity.acquire.cta.shared::cta.b64 P, [%0], %1, 0x989680;\n\t"
                 "@P bra D_%=;\n\tbra W_%=;\nD_%=:\n\t}" :: "r"(mb), "r"(ph) : "memory");
}
__device__ __forceinline__ void bulk_cp(uint32_t dst, const void* src, uint32_t bytes, uint32_t mb) {
    asm volatile("cp.async.bulk.shared::cluster.global.mbarrier::complete_tx::bytes [%0], [%1], %2, [%3];"
                 :: "r"(dst), "l"(src), "r"(bytes), "r"(mb) : "memory");
}
__device__ __forceinline__ void mma_bf16(float* d, const uint32_t* a, uint32_t b0, uint32_t b1) {
    asm volatile("mma.sync.aligned.m16n8k16.row.col.f32.bf16.bf16.f32 "
                 "{%0,%1,%2,%3},{%4,%5,%6,%7},{%8,%9},{%0,%1,%2,%3};"
                 : "+f"(d[0]), "+f"(d[1]), "+f"(d[2]), "+f"(d[3])
                 : "r"(a[0]), "r"(a[1]), "r"(a[2]), "r"(a[3]), "r"(b0), "r"(b1));
}
__device__ __forceinline__ void mma_bf16_k8(float* d, uint32_t a0, uint32_t a1, uint32_t b0) {
    asm volatile("mma.sync.aligned.m16n8k8.row.col.f32.bf16.bf16.f32 "
                 "{%0,%1,%2,%3},{%4,%5},{%6},{%0,%1,%2,%3};"
                 : "+f"(d[0]), "+f"(d[1]), "+f"(d[2]), "+f"(d[3])
                 : "r"(a0), "r"(a1), "r"(b0));
}
__device__ __forceinline__ uint32_t pack_bf2(float a, float b) {
    __nv_bfloat162 t = __floats2bfloat162_rn(a, b);
    return *reinterpret_cast<uint32_t*>(&t);
}
__device__ __forceinline__ void split_pair(float a, float b, uint32_t& hi, uint32_t& lo) {
    const __nv_bfloat16 ah = __float2bfloat16(a), bh = __float2bfloat16(b);
    hi = pack_bf2(a, b);
    lo = pack_bf2(a - __bfloat162float(ah), b - __bfloat162float(bh));
}
__device__ __forceinline__ uint4 frag_word(float v00, float v01, float v10, float v11) {
    uint4 w; uint32_t h0, l0, h1, l1;
    split_pair(v00, v01, h0, l0);
    split_pair(v10, v11, h1, l1);
    w.x = h0; w.y = h1; w.z = l0; w.w = l1;
    return w;
}

// ===================== Kernel 1: G -> fragment images =====================
__global__ __launch_bounds__(256)
void compute_G_kernel(const float* __restrict__ A, const float* __restrict__ Bp) {
    __shared__ float AsT[NM * N_FEAT];
    __shared__ float Bs[NM * N_HID];
    __shared__ float sS[N_FEAT * N_HID];
    const int ic = blockIdx.x;
    const float* Ap  = A  + (size_t)ic * N_FEAT * NM;
    const float* Bpp = Bp + (size_t)ic * NM * N_HID;
    uint4* iA = reinterpret_cast<uint4*>(g_imgA + (size_t)ic * IMGA_C);
    uint4* iB = reinterpret_cast<uint4*>(g_imgB + (size_t)ic * IMGB_C);

    for (int idx = threadIdx.x; idx < N_FEAT * NM; idx += blockDim.x) {
        const int f = idx / NM, m = idx % NM;
        AsT[m * N_FEAT + f] = Ap[idx];
    }
    for (int idx = threadIdx.x; idx < NM * N_HID; idx += blockDim.x) Bs[idx] = Bpp[idx];
    __syncthreads();
    for (int t = threadIdx.x; t < 1000; t += blockDim.x) {
        const int fp = t / 20, hp = t % 20;
        float a00 = 0.f, a01 = 0.f, a10 = 0.f, a11 = 0.f;
#pragma unroll
        for (int m = 0; m < NM; m++) {
            const float2 a = *reinterpret_cast<const float2*>(&AsT[m * N_FEAT + fp * 2]);
            const float2 b = *reinterpret_cast<const float2*>(&Bs[m * N_HID + hp * 2]);
            a00 = fmaf(a.x, b.x, a00); a01 = fmaf(a.x, b.y, a01);
            a10 = fmaf(a.y, b.x, a10); a11 = fmaf(a.y, b.y, a11);
        }
        *reinterpret_cast<float2*>(&sS[(fp * 2)     * N_HID + hp * 2]) = make_float2(a00, a01);
        *reinterpret_cast<float2*>(&sS[(fp * 2 + 1) * N_HID + hp * 2]) = make_float2(a10, a11);
    }
    __syncthreads();
    for (int widx = threadIdx.x; widx < 7 * 5 * 32; widx += blockDim.x) {
        const int kst = widx / 160, rem = widx % 160;
        const int nt = rem / 32, T = rem % 32;
        const int q = T & 3, tr = T >> 2;
        const int n = nt * 8 + tr;
        float v[2][2];
#pragma unroll
        for (int half = 0; half < 2; half++)
#pragma unroll
            for (int lo = 0; lo < 2; lo++) {
                const int f = kst * 16 + q * 2 + half * 8 + lo;
                v[half][lo] = (f < N_FEAT) ? sS[f * N_HID + n] : 0.f;
            }
        iA[widx] = frag_word(v[0][0], v[0][1], v[1][0], v[1][1]);
    }
    for (int widx = threadIdx.x; widx < 3 * 13 * 32; widx += blockDim.x) {
        const int kst = widx / 416, rem = widx % 416;
        const int nt = rem / 32, T = rem % 32;
        const int q = T & 3, tr = T >> 2;
        const int f = nt * 8 + tr;
        float v[2][2];
#pragma unroll
        for (int half = 0; half < 2; half++)
#pragma unroll
            for (int lo = 0; lo < 2; lo++) {
                const int h = kst * 16 + q * 2 + half * 8 + lo;
                v[half][lo] = (f < N_FEAT && h < N_HID) ? sS[f * N_HID + h] : 0.f;
            }
        iB[widx] = frag_word(v[0][0], v[0][1], v[1][0], v[1][1]);
    }
}

// ===================== Kernel 2: 512 thr, BT=128, bulk-DMA ring =====================
__global__ __launch_bounds__(NTHR)
void tmsspd_main_kernel(const float* __restrict__ x, const float* __restrict__ mask,
                        const float* __restrict__ bfin, float* __restrict__ out) {
    extern __shared__ char smem[];
    float* mskS  = reinterpret_cast<float*>(smem + SM_MSK);
    float* hp0   = reinterpret_cast<float*>(smem + SM_HP);
    float* hp1   = hp0 + 128 * N_HID;
    float* biasS = reinterpret_cast<float*>(smem + SM_BIAS);

    const int i   = blockIdx.y;
    const int b0  = blockIdx.x * 128;
    const int tid = threadIdx.x;
    const int w   = tid >> 5;
    const int T   = tid & 31;
    const int g   = w >> 3;
    const int tg  = tid & 255;
    const int wg  = w & 7;
    const int q   = T & 3;
    const int tr  = T >> 2;
    const int r0  = wg * 16 + tr;
    const int r1  = r0 + 8;
    const int barid = 1 + g;

    const uint32_t sb  = smem_u32(smem);
    const uint32_t rb  = sb + SM_RING + (uint32_t)g * (2 * SLOT);
    const char*    rbp = smem + SM_RING + g * (2 * SLOT);
    const uint32_t mb0 = sb + SM_MB + (uint32_t)(g * 2) * 8;
    const uint32_t mb1 = mb0 + 8;
    const bool lead = (tg == 0);
    uint32_t par0 = 0, par1 = 0;

    const unsigned char* imgAg = g_imgA + (size_t)(i * NC) * IMGA_C + (size_t)(g * 10) * SLOTA;
    const unsigned char* imgBg = g_imgB + (size_t)(i * NC) * IMGB_C + (size_t)(g * 10) * SLOTB;

    if (lead) { mbar_init(mb0, 1); mbar_init(mb1, 1); }

    for (int idx = tid; idx < 128 * NC; idx += NTHR) {
        const int r = idx / NC, c = idx % NC;
        mskS[c * 128 + r] = mask[((size_t)(b0 + r) * N_INST + i) * NC + c];
    }
    if (tid < N_FEAT) biasS[tid] = bfin[i * N_FEAT + tid];

    // X fragments: kst 0..5 k16, kst6 k8 (f 96..103)
    uint32_t xhi[6][4], xlo[6][4], xh6[2], xl6[2];
    {
        const float* xr0 = x + ((size_t)(b0 + r0) * N_INST + i) * N_FEAT;
        const float* xr1 = x + ((size_t)(b0 + r1) * N_INST + i) * N_FEAT;
#pragma unroll
        for (int kst = 0; kst < 6; kst++) {
#pragma unroll
            for (int half = 0; half < 2; half++) {
                const int kk = kst * 16 + q * 2 + half * 8;
                const float2 v0 = *reinterpret_cast<const float2*>(xr0 + kk);
                const float2 v1 = *reinterpret_cast<const float2*>(xr1 + kk);
                split_pair(v0.x, v0.y, xhi[kst][half * 2],     xlo[kst][half * 2]);
                split_pair(v1.x, v1.y, xhi[kst][half * 2 + 1], xlo[kst][half * 2 + 1]);
            }
        }
        const int kk = 96 + q * 2;
        float2 v0 = make_float2(0.f, 0.f), v1 = make_float2(0.f, 0.f);
        if (kk < N_FEAT) {
            v0 = *reinterpret_cast<const float2*>(xr0 + kk);
            v1 = *reinterpret_cast<const float2*>(xr1 + kk);
        }
        split_pair(v0.x, v0.y, xh6[0], xl6[0]);
        split_pair(v1.x, v1.y, xh6[1], xl6[1]);
    }
    __syncthreads();   // mask/bias + mbar init visible

    // prologue: bulk-stage A pairs 0,1
    if (lead) {
        mbar_expect(mb0, SLOTA); bulk_cp(rb,        imgAg,         SLOTA, mb0);
        mbar_expect(mb1, SLOTA); bulk_cp(rb + SLOT, imgAg + SLOTA, SLOTA, mb1);
    }

    // ================= Phase A: 10 pair-iterations =================
    float hacc[5][4];
#pragma unroll
    for (int nt = 0; nt < 5; nt++)
#pragma unroll
        for (int j = 0; j < 4; j++) hacc[nt][j] = 0.f;

    for (int cp = 0; cp < 10; cp++) {
        if (cp & 1) { mbar_wait(mb1, par1); par1 ^= 1; }
        else        { mbar_wait(mb0, par0); par0 ^= 1; }

        const char* base = rbp + (cp & 1) * SLOT;
#pragma unroll
        for (int cc = 0; cc < 2; cc++) {
            const int c = 2 * (g * 10 + cp) + cc;
            const char* buf = base + cc * IMGA_C;
            float d[5][4];
#pragma unroll
            for (int nt = 0; nt < 5; nt++)
#pragma unroll
                for (int j = 0; j < 4; j++) d[nt][j] = 0.f;
#pragma unroll
            for (int kst = 0; kst < 6; kst++) {
                uint4 wv[5];
#pragma unroll
                for (int nt = 0; nt < 5; nt++)
                    wv[nt] = *reinterpret_cast<const uint4*>(buf + (((kst * 5 + nt) * 32 + T) << 4));
#pragma unroll
                for (int nt = 0; nt < 5; nt++) mma_bf16(d[nt], xhi[kst], wv[nt].x, wv[nt].y);
#pragma unroll
                for (int nt = 0; nt < 5; nt++) mma_bf16(d[nt], xhi[kst], wv[nt].z, wv[nt].w);
#pragma unroll
                for (int nt = 0; nt < 5; nt++) mma_bf16(d[nt], xlo[kst], wv[nt].x, wv[nt].y);
            }
            {
                uint4 wv[5];
#pragma unroll
                for (int nt = 0; nt < 5; nt++)
                    wv[nt] = *reinterpret_cast<const uint4*>(buf + (((6 * 5 + nt) * 32 + T) << 4));
#pragma unroll
                for (int nt = 0; nt < 5; nt++) mma_bf16_k8(d[nt], xh6[0], xh6[1], wv[nt].x);
#pragma unroll
                for (int nt = 0; nt < 5; nt++) mma_bf16_k8(d[nt], xh6[0], xh6[1], wv[nt].z);
#pragma unroll
                for (int nt = 0; nt < 5; nt++) mma_bf16_k8(d[nt], xl6[0], xl6[1], wv[nt].x);
            }
            const float m0 = mskS[c * 128 + r0];
            const float m1 = mskS[c * 128 + r1];
#pragma unroll
            for (int nt = 0; nt < 5; nt++) {
                hacc[nt][0] = fmaf(m0, d[nt][0], hacc[nt][0]);
                hacc[nt][1] = fmaf(m0, d[nt][1], hacc[nt][1]);
                hacc[nt][2] = fmaf(m1, d[nt][2], hacc[nt][2]);
                hacc[nt][3] = fmaf(m1, d[nt][3], hacc[nt][3]);
            }
        }
        BARG(barid);   // whole group done with slot cp&1
        if (lead && cp + 2 <= 9) {
            const uint32_t mb = (cp & 1) ? mb1 : mb0;
            mbar_expect(mb, SLOTA);
            bulk_cp(rb + (cp & 1) * SLOT, imgAg + (size_t)(cp + 2) * SLOTA, SLOTA, mb);
        }
    }

    // group partial h; stage B pairs 0,1 (both slots free after last BARG)
    {
        float* hp = g ? hp1 : hp0;
#pragma unroll
        for (int nt = 0; nt < 5; nt++) {
            const int col = nt * 8 + q * 2;
            *reinterpret_cast<float2*>(&hp[r0 * N_HID + col]) = make_float2(hacc[nt][0], hacc[nt][1]);
            *reinterpret_cast<float2*>(&hp[r1 * N_HID + col]) = make_float2(hacc[nt][2], hacc[nt][3]);
        }
    }
    if (lead) {
        mbar_expect(mb0, SLOTB); bulk_cp(rb,        imgBg,         SLOTB, mb0);
        mbar_expect(mb1, SLOTB); bulk_cp(rb + SLOT, imgBg + SLOTB, SLOTB, mb1);
    }
    __syncthreads();   // both partials visible

    // h fragments: kst 0,1 k16; kst2 k8
    uint32_t hh[2][4], hl[2][4], hh2[2], hl2[2];
#pragma unroll
    for (int kst = 0; kst < 2; kst++) {
#pragma unroll
        for (int half = 0; half < 2; half++) {
            const int kk = kst * 16 + q * 2 + half * 8;
            const float2 a0  = *reinterpret_cast<const float2*>(&hp0[r0 * N_HID + kk]);
            const float2 b0v = *reinterpret_cast<const float2*>(&hp1[r0 * N_HID + kk]);
            const float2 a1  = *reinterpret_cast<const float2*>(&hp0[r1 * N_HID + kk]);
            const float2 b1v = *reinterpret_cast<const float2*>(&hp1[r1 * N_HID + kk]);
            split_pair(a0.x + b0v.x, a0.y + b0v.y, hh[kst][half * 2],     hl[kst][half * 2]);
            split_pair(a1.x + b1v.x, a1.y + b1v.y, hh[kst][half * 2 + 1], hl[kst][half * 2 + 1]);
        }
    }
    {
        const int kk = 32 + q * 2;
        const float2 a0  = *reinterpret_cast<const float2*>(&hp0[r0 * N_HID + kk]);
        const float2 b0v = *reinterpret_cast<const float2*>(&hp1[r0 * N_HID + kk]);
        const float2 a1  = *reinterpret_cast<const float2*>(&hp0[r1 * N_HID + kk]);
        const float2 b1v = *reinterpret_cast<const float2*>(&hp1[r1 * N_HID + kk]);
        split_pair(a0.x + b0v.x, a0.y + b0v.y, hh2[0], hl2[0]);
        split_pair(a1.x + b1v.x, a1.y + b1v.y, hh2[1], hl2[1]);
    }

    // ================= Phase B: 10 pair-iterations =================
    float oacc[13][4];
#pragma unroll
    for (int nt = 0; nt < 13; nt++)
#pragma unroll
        for (int j = 0; j < 4; j++) oacc[nt][j] = 0.f;

    for (int cp = 0; cp < 10; cp++) {
        if (cp & 1) { mbar_wait(mb1, par1); par1 ^= 1; }
        else        { mbar_wait(mb0, par0); par0 ^= 1; }

        const char* base = rbp + (cp & 1) * SLOT;
#pragma unroll
        for (int cc = 0; cc < 2; cc++) {
            const int c = 2 * (g * 10 + cp) + cc;
            const char* buf = base + cc * IMGB_C;
            const uint32_t keep0 = (mskS[c * 128 + r0] != 0.f) ? 0xFFFFFFFFu : 0u;
            const uint32_t keep1 = (mskS[c * 128 + r1] != 0.f) ? 0xFFFFFFFFu : 0u;
#pragma unroll
            for (int kst = 0; kst < 2; kst++) {
                uint32_t ah[4], al[4];
                ah[0] = hh[kst][0] & keep0; ah[1] = hh[kst][1] & keep1;
                ah[2] = hh[kst][2] & keep0; ah[3] = hh[kst][3] & keep1;
                al[0] = hl[kst][0] & keep0; al[1] = hl[kst][1] & keep1;
                al[2] = hl[kst][2] & keep0; al[3] = hl[kst][3] & keep1;
                {
                    uint4 wv[7];
#pragma unroll
                    for (int j = 0; j < 7; j++)
                        wv[j] = *reinterpret_cast<const uint4*>(buf + (((kst * 13 + j) * 32 + T) << 4));
#pragma unroll
                    for (int j = 0; j < 7; j++) mma_bf16(oacc[j], ah, wv[j].x, wv[j].y);
#pragma unroll
                    for (int j = 0; j < 7; j++) mma_bf16(oacc[j], ah, wv[j].z, wv[j].w);
#pragma unroll
                    for (int j = 0; j < 7; j++) mma_bf16(oacc[j], al, wv[j].x, wv[j].y);
                }
                {
                    uint4 wv[6];
#pragma unroll
                    for (int j = 0; j < 6; j++)
                        wv[j] = *reinterpret_cast<const uint4*>(buf + (((kst * 13 + 7 + j) * 32 + T) << 4));
#pragma unroll
                    for (int j = 0; j < 6; j++) mma_bf16(oacc[7 + j], ah, wv[j].x, wv[j].y);
#pragma unroll
                    for (int j = 0; j < 6; j++) mma_bf16(oacc[7 + j], ah, wv[j].z, wv[j].w);
#pragma unroll
                    for (int j = 0; j < 6; j++) mma_bf16(oacc[7 + j], al, wv[j].x, wv[j].y);
                }
            }
            {
                const uint32_t a0 = hh2[0] & keep0, a1 = hh2[1] & keep1;
                const uint32_t c0 = hl2[0] & keep0, c1 = hl2[1] & keep1;
                {
                    uint4 wv[7];
#pragma unroll
                    for (int j = 0; j < 7; j++)
                        wv[j] = *reinterpret_cast<const uint4*>(buf + (((2 * 13 + j) * 32 + T) << 4));
#pragma unroll
                    for (int j = 0; j < 7; j++) mma_bf16_k8(oacc[j], a0, a1, wv[j].x);
#pragma unroll
                    for (int j = 0; j < 7; j++) mma_bf16_k8(oacc[j], a0, a1, wv[j].z);
#pragma unroll
                    for (int j = 0; j < 7; j++) mma_bf16_k8(oacc[j], c0, c1, wv[j].x);
                }
                {
                    uint4 wv[6];
#pragma unroll
                    for (int j = 0; j < 6; j++)
                        wv[j] = *reinterpret_cast<const uint4*>(buf + (((2 * 13 + 7 + j) * 32 + T) << 4));
#pragma unroll
                    for (int j = 0; j < 6; j++) mma_bf16_k8(oacc[7 + j], a0, a1, wv[j].x);
#pragma unroll
                    for (int j = 0; j < 6; j++) mma_bf16_k8(oacc[7 + j], a0, a1, wv[j].z);
#pragma unroll
                    for (int j = 0; j < 6; j++) mma_bf16_k8(oacc[7 + j], c0, c1, wv[j].x);
                }
            }
        }
        BARG(barid);
        if (lead && cp + 2 <= 9) {
            const uint32_t mb = (cp & 1) ? mb1 : mb0;
            mbar_expect(mb, SLOTB);
            bulk_cp(rb + (cp & 1) * SLOT, imgBg + (size_t)(cp + 2) * SLOTB, SLOTB, mb);
        }
    }

    // ================= cross-group reduce + epilogue =================
    float* stash = reinterpret_cast<float*>(smem);   // ring dead
    __syncthreads();
    if (g == 1) {
#pragma unroll
        for (int nt = 0; nt < 13; nt++) {
            const int col = nt * 8 + q * 2;
            *reinterpret_cast<float2*>(&stash[r0 * 104 + col]) = make_float2(oacc[nt][0], oacc[nt][1]);
            *reinterpret_cast<float2*>(&stash[r1 * 104 + col]) = make_float2(oacc[nt][2], oacc[nt][3]);
        }
    }
    __syncthreads();
    if (g == 0) {
        float* o0 = out + ((size_t)(b0 + r0) * N_INST + i) * N_FEAT;
        float* o1 = out + ((size_t)(b0 + r1) * N_INST + i) * N_FEAT;
#pragma unroll
        for (int nt = 0; nt < 13; nt++) {
            const int col = nt * 8 + q * 2;
            if (col < N_FEAT) {
                const float2 s0 = *reinterpret_cast<const float2*>(&stash[r0 * 104 + col]);
                const float2 s1 = *reinterpret_cast<const float2*>(&stash[r1 * 104 + col]);
                const float2 bf = *reinterpret_cast<const float2*>(&biasS[col]);
                float2 a, b;
                a.x = fmaxf(oacc[nt][0] + s0.x + bf.x, 0.f);
                a.y = fmaxf(oacc[nt][1] + s0.y + bf.y, 0.f);
                b.x = fmaxf(oacc[nt][2] + s1.x + bf.x, 0.f);
                b.y = fmaxf(oacc[nt][3] + s1.y + bf.y, 0.f);
                *reinterpret_cast<float2*>(o0 + col) = a;
                *reinterpret_cast<float2*>(o1 + col) = b;
            }
        }
    }
}

// ---------------------------------------------------------------------------
extern "C" void kernel_launch(void* const* d_in, const int* in_sizes, int n_in,
                              void* d_out, int out_size) {
    (void)in_sizes; (void)n_in; (void)out_size;
    const float* x    = (const float*)d_in[0];
    const float* mask = (const float*)d_in[1];
    const float* A    = (const float*)d_in[2];
    const float* Bp   = (const float*)d_in[3];
    const float* bfin = (const float*)d_in[4];
    float* out = (float*)d_out;

    cudaFuncSetAttribute(tmsspd_main_kernel,
                         cudaFuncAttributeMaxDynamicSharedMemorySize, SM_TOTAL);

    compute_G_kernel<<<N_INST * NC, 256>>>(A, Bp);

    dim3 grid(B_SZ / 128, N_INST);
    tmsspd_main_kernel<<<grid, NTHR, SM_TOTAL>>>(x, mask, bfin, out);
}

// round 14
// speedup vs baseline: 1.1473x; 1.0864x over previous
#include <cuda_runtime.h>
#include <cuda_bf16.h>
#include <cstdint>

#define B_SZ   2048
#define N_INST 8
#define N_FEAT 100
#define N_HID  40
#define NM     41
#define NC     40
#define NTHR   512

#define IMGA_C 17920
#define IMGB_C 19968
#define SLOTA  (2*IMGA_C)
#define SLOTB  (2*IMGB_C)

// ---- smem map (byte offsets), phases overlay ----
#define SM_RING  0                 // A: 2x35840=71680 ; B: 2x39936=79872
#define SM_XS    71680             // X bf16 [129][112] hi+lo = 57792 -> 129472
#define XS_LO    28896
#define SM_HACC  129472            // 2 x 129*40*4 = 41280 -> 170752
#define SM_OS    79872             // 2 x 129*104*4 = 107328 -> 187200 (phase B)
#define SM_HS    187200            // h bf16 [129][48] hi+lo = 24768 -> 211968
#define HS_LO    12384
#define SM_RL    211968            // rowlist u8 [40][144] = 5760
#define SM_CNT   217728            // ntiles int[40]
#define SM_BIAS  217888            // 400
#define SM_MB    218288            // 2 mbarriers
#define SM_TOTAL 218368

__device__ __align__(16) unsigned char g_imgA[N_INST * NC * IMGA_C];
__device__ __align__(16) unsigned char g_imgB[N_INST * NC * IMGB_C];

// ===================== helpers =====================
__device__ __forceinline__ uint32_t smem_u32(const void* p) {
    return (uint32_t)__cvta_generic_to_shared(p);
}
__device__ __forceinline__ void mbar_init(uint32_t mb, uint32_t n) {
    asm volatile("mbarrier.init.shared.b64 [%0], %1;" :: "r"(mb), "r"(n) : "memory");
}
__device__ __forceinline__ void mbar_expect(uint32_t mb, uint32_t bytes) {
    asm volatile("mbarrier.arrive.expect_tx.shared.b64 _, [%0], %1;" :: "r"(mb), "r"(bytes) : "memory");
}
__device__ __forceinline__ void mbar_wait(uint32_t mb, uint32_t ph) {
    asm volatile("{\n\t.reg .pred P;\nW_%=:\n\t"
                 "mbarrier.try_wait.parity.acquire.cta.shared::cta.b64 P, [%0], %1, 0x989680;\n\t"
                 "@P bra D_%=;\n\tbra W_%=;\nD_%=:\n\t}" :: "r"(mb), "r"(ph) : "memory");
}
__device__ __forceinline__ void bulk_cp(uint32_t dst, const void* src, uint32_t bytes, uint32_t mb) {
    asm volatile("cp.async.bulk.shared::cluster.global.mbarrier::complete_tx::bytes [%0], [%1], %2, [%3];"
                 :: "r"(dst), "l"(src), "r"(bytes), "r"(mb) : "memory");
}
__device__ __forceinline__ void mma_bf16(float* d, const uint32_t* a, uint32_t b0, uint32_t b1) {
    asm volatile("mma.sync.aligned.m16n8k16.row.col.f32.bf16.bf16.f32 "
                 "{%0,%1,%2,%3},{%4,%5,%6,%7},{%8,%9},{%0,%1,%2,%3};"
                 : "+f"(d[0]), "+f"(d[1]), "+f"(d[2]), "+f"(d[3])
                 : "r"(a[0]), "r"(a[1]), "r"(a[2]), "r"(a[3]), "r"(b0), "r"(b1));
}
__device__ __forceinline__ void mma_bf16_k8(float* d, uint32_t a0, uint32_t a1, uint32_t b0) {
    asm volatile("mma.sync.aligned.m16n8k8.row.col.f32.bf16.bf16.f32 "
                 "{%0,%1,%2,%3},{%4,%5},{%6},{%0,%1,%2,%3};"
                 : "+f"(d[0]), "+f"(d[1]), "+f"(d[2]), "+f"(d[3])
                 : "r"(a0), "r"(a1), "r"(b0));
}
__device__ __forceinline__ void ldm_x4(uint32_t* r, uint32_t a) {
    asm volatile("ldmatrix.sync.aligned.m8n8.x4.shared.b16 {%0,%1,%2,%3}, [%4];"
                 : "=r"(r[0]), "=r"(r[1]), "=r"(r[2]), "=r"(r[3]) : "r"(a));
}
__device__ __forceinline__ void ldm_x2(uint32_t* r, uint32_t a) {
    asm volatile("ldmatrix.sync.aligned.m8n8.x2.shared.b16 {%0,%1}, [%2];"
                 : "=r"(r[0]), "=r"(r[1]) : "r"(a));
}
__device__ __forceinline__ uint32_t pack_bf2(float a, float b) {
    __nv_bfloat162 t = __floats2bfloat162_rn(a, b);
    return *reinterpret_cast<uint32_t*>(&t);
}
__device__ __forceinline__ void split_pair(float a, float b, uint32_t& hi, uint32_t& lo) {
    const __nv_bfloat16 ah = __float2bfloat16(a), bh = __float2bfloat16(b);
    hi = pack_bf2(a, b);
    lo = pack_bf2(a - __bfloat162float(ah), b - __bfloat162float(bh));
}
__device__ __forceinline__ uint4 frag_word(float v00, float v01, float v10, float v11) {
    uint4 w; uint32_t h0, l0, h1, l1;
    split_pair(v00, v01, h0, l0);
    split_pair(v10, v11, h1, l1);
    w.x = h0; w.y = h1; w.z = l0; w.w = l1;
    return w;
}

// ===================== Kernel 1: G -> fragment images (unchanged) =====================
__global__ __launch_bounds__(256)
void compute_G_kernel(const float* __restrict__ A, const float* __restrict__ Bp) {
    __shared__ float AsT[NM * N_FEAT];
    __shared__ float Bs[NM * N_HID];
    __shared__ float sS[N_FEAT * N_HID];
    const int ic = blockIdx.x;
    const float* Ap  = A  + (size_t)ic * N_FEAT * NM;
    const float* Bpp = Bp + (size_t)ic * NM * N_HID;
    uint4* iA = reinterpret_cast<uint4*>(g_imgA + (size_t)ic * IMGA_C);
    uint4* iB = reinterpret_cast<uint4*>(g_imgB + (size_t)ic * IMGB_C);

    for (int idx = threadIdx.x; idx < N_FEAT * NM; idx += blockDim.x) {
        const int f = idx / NM, m = idx % NM;
        AsT[m * N_FEAT + f] = Ap[idx];
    }
    for (int idx = threadIdx.x; idx < NM * N_HID; idx += blockDim.x) Bs[idx] = Bpp[idx];
    __syncthreads();
    for (int t = threadIdx.x; t < 1000; t += blockDim.x) {
        const int fp = t / 20, hp = t % 20;
        float a00 = 0.f, a01 = 0.f, a10 = 0.f, a11 = 0.f;
#pragma unroll
        for (int m = 0; m < NM; m++) {
            const float2 a = *reinterpret_cast<const float2*>(&AsT[m * N_FEAT + fp * 2]);
            const float2 b = *reinterpret_cast<const float2*>(&Bs[m * N_HID + hp * 2]);
            a00 = fmaf(a.x, b.x, a00); a01 = fmaf(a.x, b.y, a01);
            a10 = fmaf(a.y, b.x, a10); a11 = fmaf(a.y, b.y, a11);
        }
        *reinterpret_cast<float2*>(&sS[(fp * 2)     * N_HID + hp * 2]) = make_float2(a00, a01);
        *reinterpret_cast<float2*>(&sS[(fp * 2 + 1) * N_HID + hp * 2]) = make_float2(a10, a11);
    }
    __syncthreads();
    for (int widx = threadIdx.x; widx < 7 * 5 * 32; widx += blockDim.x) {
        const int kst = widx / 160, rem = widx % 160;
        const int nt = rem / 32, T = rem % 32;
        const int q = T & 3, tr = T >> 2;
        const int n = nt * 8 + tr;
        float v[2][2];
#pragma unroll
        for (int half = 0; half < 2; half++)
#pragma unroll
            for (int lo = 0; lo < 2; lo++) {
                const int f = kst * 16 + q * 2 + half * 8 + lo;
                v[half][lo] = (f < N_FEAT) ? sS[f * N_HID + n] : 0.f;
            }
        iA[widx] = frag_word(v[0][0], v[0][1], v[1][0], v[1][1]);
    }
    for (int widx = threadIdx.x; widx < 3 * 13 * 32; widx += blockDim.x) {
        const int kst = widx / 416, rem = widx % 416;
        const int nt = rem / 32, T = rem % 32;
        const int q = T & 3, tr = T >> 2;
        const int f = nt * 8 + tr;
        float v[2][2];
#pragma unroll
        for (int half = 0; half < 2; half++)
#pragma unroll
            for (int lo = 0; lo < 2; lo++) {
                const int h = kst * 16 + q * 2 + half * 8 + lo;
                v[half][lo] = (f < N_FEAT && h < N_HID) ? sS[f * N_HID + h] : 0.f;
            }
        iB[widx] = frag_word(v[0][0], v[0][1], v[1][0], v[1][1]);
    }
}

// ===================== Kernel 2: sparse gather/scatter MMA =====================
__global__ __launch_bounds__(NTHR)
void tmsspd_main_kernel(const float* __restrict__ x, const float* __restrict__ mask,
                        const float* __restrict__ bfin, float* __restrict__ out) {
    extern __shared__ char smem[];
    const uint32_t sb = smem_u32(smem);
    unsigned char* RL = reinterpret_cast<unsigned char*>(smem + SM_RL);
    int*   CNT   = reinterpret_cast<int*>(smem + SM_CNT);
    float* biasS = reinterpret_cast<float*>(smem + SM_BIAS);
    float* hA[2] = { reinterpret_cast<float*>(smem + SM_HACC),
                     reinterpret_cast<float*>(smem + SM_HACC + 20640) };
    float* oS[2] = { reinterpret_cast<float*>(smem + SM_OS),
                     reinterpret_cast<float*>(smem + SM_OS + 53664) };

    const int i   = blockIdx.y;
    const int b0  = blockIdx.x * 128;
    const int tid = threadIdx.x;
    const int w   = tid >> 5;
    const int T   = tid & 31;
    const int q   = T & 3;
    const int jj  = ((T >> 3) & 1) * 8 + (T & 7);   // ldmatrix row slot
    const int kh  = (T >> 4) * 16;                  // ldmatrix k-half byte off
    const uint32_t mb0 = sb + SM_MB, mb1 = mb0 + 8;
    uint32_t par0 = 0, par1 = 0;
    const bool lead = (tid == 0);

    const unsigned char* imgA = g_imgA + (size_t)(i * NC) * IMGA_C;
    const unsigned char* imgB = g_imgB + (size_t)(i * NC) * IMGB_C;

    if (lead) { mbar_init(mb0, 1); mbar_init(mb1, 1); }

    // ---- build active-row lists (warp per c) ----
    for (int c = w; c < NC; c += 16) {
        int base = 0;
#pragma unroll
        for (int ch = 0; ch < 4; ch++) {
            const int r = ch * 32 + T;
            const float m = mask[((size_t)(b0 + r) * N_INST + i) * NC + c];
            const unsigned bal = __ballot_sync(0xffffffffu, m != 0.f);
            const int pos = __popc(bal & ((1u << T) - 1u));
            if (m != 0.f) RL[c * 144 + base + pos] = (unsigned char)r;
            base += __popc(bal);
        }
        const int nt = (base + 15) >> 4;
        for (int j = base + T; j < nt * 16; j += 32) RL[c * 144 + j] = 128;
        if (T == 0) CNT[c] = nt;
    }
    // ---- XS: x bf16 split [129][112], row 128 & k>=100 zero ----
    for (int idx = tid; idx < 129 * 56; idx += NTHR) {     // pairs
        const int r = idx / 56, kp = idx % 56;
        float2 v = make_float2(0.f, 0.f);
        if (r < 128 && kp < 50)
            v = *reinterpret_cast<const float2*>(&x[((size_t)(b0 + r) * N_INST + i) * N_FEAT + kp * 2]);
        uint32_t hi, lo; split_pair(v.x, v.y, hi, lo);
        *reinterpret_cast<uint32_t*>(smem + SM_XS + r * 224 + kp * 4) = hi;
        *reinterpret_cast<uint32_t*>(smem + SM_XS + XS_LO + r * 224 + kp * 4) = lo;
    }
    for (int idx = tid; idx < 2 * 5160; idx += NTHR) hA[idx / 5160][idx % 5160] = 0.f;
    if (tid < N_FEAT) biasS[tid] = bfin[i * N_FEAT + tid];
    __syncthreads();

    if (lead) {
        mbar_expect(mb0, SLOTA); bulk_cp(sb + SM_RING,         imgA,         SLOTA, mb0);
        mbar_expect(mb1, SLOTA); bulk_cp(sb + SM_RING + SLOTA, imgA + SLOTA, SLOTA, mb1);
    }

    // ================= Phase A =================
    for (int s = 0; s < 20; s++) {
        if (s & 1) { mbar_wait(mb1, par1); par1 ^= 1; }
        else       { mbar_wait(mb0, par0); par0 ^= 1; }
        const int c0 = 2 * s, n0 = CNT[c0], n1 = CNT[c0 + 1];
        const char* slot = smem + SM_RING + (s & 1) * SLOTA;

        for (int t = w; t < n0 + n1; t += 16) {
            const int c  = (t < n0) ? c0 : c0 + 1;
            const int tt = (t < n0) ? t : t - n0;
            const char* buf = slot + ((t < n0) ? 0 : IMGA_C);
            const unsigned char* rl = RL + c * 144 + tt * 16;
            const int myrow = rl[jj];
            const uint32_t ab = sb + SM_XS + myrow * 224 + kh;

            float d[5][4];
#pragma unroll
            for (int nt = 0; nt < 5; nt++)
#pragma unroll
                for (int j = 0; j < 4; j++) d[nt][j] = 0.f;

#pragma unroll
            for (int kst = 0; kst < 6; kst++) {
                uint32_t ah[4], al[4];
                ldm_x4(ah, ab + kst * 32);
                ldm_x4(al, ab + XS_LO + kst * 32);
                uint4 wv[5];
#pragma unroll
                for (int nt = 0; nt < 5; nt++)
                    wv[nt] = *reinterpret_cast<const uint4*>(buf + (((kst * 5 + nt) * 32 + T) << 4));
#pragma unroll
                for (int nt = 0; nt < 5; nt++) mma_bf16(d[nt], ah, wv[nt].x, wv[nt].y);
#pragma unroll
                for (int nt = 0; nt < 5; nt++) mma_bf16(d[nt], ah, wv[nt].z, wv[nt].w);
#pragma unroll
                for (int nt = 0; nt < 5; nt++) mma_bf16(d[nt], al, wv[nt].x, wv[nt].y);
            }
            {   // k8 tail (f 96..103)
                uint32_t ah[2], al[2];
                ldm_x2(ah, sb + SM_XS + myrow * 224 + 192);
                ldm_x2(al, sb + SM_XS + XS_LO + myrow * 224 + 192);
                uint4 wv[5];
#pragma unroll
                for (int nt = 0; nt < 5; nt++)
                    wv[nt] = *reinterpret_cast<const uint4*>(buf + (((30 + nt) * 32 + T) << 4));
#pragma unroll
                for (int nt = 0; nt < 5; nt++) mma_bf16_k8(d[nt], ah[0], ah[1], wv[nt].x);
#pragma unroll
                for (int nt = 0; nt < 5; nt++) mma_bf16_k8(d[nt], ah[0], ah[1], wv[nt].z);
#pragma unroll
                for (int nt = 0; nt < 5; nt++) mma_bf16_k8(d[nt], al[0], al[1], wv[nt].x);
            }
            // scatter-add (parity buffer; rows disjoint across tiles)
            float* hb = hA[c & 1];
            const int ra = rl[T >> 2], rb = rl[(T >> 2) + 8];
#pragma unroll
            for (int nt = 0; nt < 5; nt++) {
                const int col = nt * 8 + q * 2;
                float2* pa = reinterpret_cast<float2*>(&hb[ra * 40 + col]);
                float2 va = *pa; va.x += d[nt][0]; va.y += d[nt][1]; *pa = va;
                float2* pb = reinterpret_cast<float2*>(&hb[rb * 40 + col]);
                float2 vb = *pb; vb.x += d[nt][2]; vb.y += d[nt][3]; *pb = vb;
            }
        }
        __syncthreads();
        if (lead && s + 2 < 20) {
            const uint32_t mb = (s & 1) ? mb1 : mb0;
            mbar_expect(mb, SLOTA);
            bulk_cp(sb + SM_RING + (s & 1) * SLOTA, imgA + (size_t)(s + 2) * SLOTA, SLOTA, mb);
        }
    }

    // ---- stage B pair 0,1 ; build HS from hA sums ; zero oS ----
    if (lead) {
        mbar_expect(mb0, SLOTB); bulk_cp(sb + SM_RING,         imgB,         SLOTB, mb0);
        mbar_expect(mb1, SLOTB); bulk_cp(sb + SM_RING + SLOTB, imgB + SLOTB, SLOTB, mb1);
    }
    for (int idx = tid; idx < 129 * 24; idx += NTHR) {     // pairs of 48-wide rows
        const int r = idx / 24, kp = idx % 24;
        float2 v = make_float2(0.f, 0.f);
        if (r < 128 && kp < 20) {
            v.x = hA[0][r * 40 + kp * 2]     + hA[1][r * 40 + kp * 2];
            v.y = hA[0][r * 40 + kp * 2 + 1] + hA[1][r * 40 + kp * 2 + 1];
        }
        uint32_t hi, lo; split_pair(v.x, v.y, hi, lo);
        *reinterpret_cast<uint32_t*>(smem + SM_HS + r * 96 + kp * 4) = hi;
        *reinterpret_cast<uint32_t*>(smem + SM_HS + HS_LO + r * 96 + kp * 4) = lo;
    }
    __syncthreads();                                        // HS done before oS overwrite
    for (int idx = tid; idx < 2 * 13416; idx += NTHR) oS[idx / 13416][idx % 13416] = 0.f;
    __syncthreads();

    // ================= Phase B =================
    for (int s = 0; s < 20; s++) {
        if (s & 1) { mbar_wait(mb1, par1); par1 ^= 1; }
        else       { mbar_wait(mb0, par0); par0 ^= 1; }
        const int c0 = 2 * s, n0 = CNT[c0], n1 = CNT[c0 + 1];
        const char* slot = smem + SM_RING + (s & 1) * SLOTB;

        for (int t = w; t < n0 + n1; t += 16) {
            const int c  = (t < n0) ? c0 : c0 + 1;
            const int tt = (t < n0) ? t : t - n0;
            const char* buf = slot + ((t < n0) ? 0 : IMGB_C);
            const unsigned char* rl = RL + c * 144 + tt * 16;
            const int myrow = rl[jj];
            const uint32_t ab = sb + SM_HS + myrow * 96 + kh;

            float d[13][4];
#pragma unroll
            for (int nt = 0; nt < 13; nt++)
#pragma unroll
                for (int j = 0; j < 4; j++) d[nt][j] = 0.f;

#pragma unroll
            for (int kst = 0; kst < 2; kst++) {
                uint32_t ah[4], al[4];
                ldm_x4(ah, ab + kst * 32);
                ldm_x4(al, ab + HS_LO + kst * 32);
                {
                    uint4 wv[7];
#pragma unroll
                    for (int j = 0; j < 7; j++)
                        wv[j] = *reinterpret_cast<const uint4*>(buf + (((kst * 13 + j) * 32 + T) << 4));
#pragma unroll
                    for (int j = 0; j < 7; j++) mma_bf16(d[j], ah, wv[j].x, wv[j].y);
#pragma unroll
                    for (int j = 0; j < 7; j++) mma_bf16(d[j], ah, wv[j].z, wv[j].w);
#pragma unroll
                    for (int j = 0; j < 7; j++) mma_bf16(d[j], al, wv[j].x, wv[j].y);
                }
                {
                    uint4 wv[6];
#pragma unroll
                    for (int j = 0; j < 6; j++)
                        wv[j] = *reinterpret_cast<const uint4*>(buf + (((kst * 13 + 7 + j) * 32 + T) << 4));
#pragma unroll
                    for (int j = 0; j < 6; j++) mma_bf16(d[7 + j], ah, wv[j].x, wv[j].y);
#pragma unroll
                    for (int j = 0; j < 6; j++) mma_bf16(d[7 + j], ah, wv[j].z, wv[j].w);
#pragma unroll
                    for (int j = 0; j < 6; j++) mma_bf16(d[7 + j], al, wv[j].x, wv[j].y);
                }
            }
            {   // k8 tail (h 32..39)
                uint32_t ah[2], al[2];
                ldm_x2(ah, sb + SM_HS + myrow * 96 + 64);
                ldm_x2(al, sb + SM_HS + HS_LO + myrow * 96 + 64);
#pragma unroll
                for (int j = 0; j < 13; j++) {
                    const uint4 wv = *reinterpret_cast<const uint4*>(buf + (((26 + j) * 32 + T) << 4));
                    mma_bf16_k8(d[j], ah[0], ah[1], wv.x);
                    mma_bf16_k8(d[j], ah[0], ah[1], wv.z);
                    mma_bf16_k8(d[j], al[0], al[1], wv.x);
                }
            }
            // scatter-add into parity out accumulator
            float* ob = oS[c & 1];
            const int ra = rl[T >> 2], rb = rl[(T >> 2) + 8];
#pragma unroll
            for (int nt = 0; nt < 13; nt++) {
                const int col = nt * 8 + q * 2;
                float2* pa = reinterpret_cast<float2*>(&ob[ra * 104 + col]);
                float2 va = *pa; va.x += d[nt][0]; va.y += d[nt][1]; *pa = va;
                float2* pb = reinterpret_cast<float2*>(&ob[rb * 104 + col]);
                float2 vb = *pb; vb.x += d[nt][2]; vb.y += d[nt][3]; *pb = vb;
            }
        }
        __syncthreads();
        if (lead && s + 2 < 20) {
            const uint32_t mb = (s & 1) ? mb1 : mb0;
            mbar_expect(mb, SLOTB);
            bulk_cp(sb + SM_RING + (s & 1) * SLOTB, imgB + (size_t)(s + 2) * SLOTB, SLOTB, mb);
        }
    }

    // ================= epilogue =================
    for (int idx = tid; idx < 128 * 50; idx += NTHR) {
        const int r = idx / 50, f = (idx % 50) * 2;
        float2 a = *reinterpret_cast<const float2*>(&oS[0][r * 104 + f]);
        float2 b = *reinterpret_cast<const float2*>(&oS[1][r * 104 + f]);
        float2 bf = *reinterpret_cast<const float2*>(&biasS[f]);
        float2 o;
        o.x = fmaxf(a.x + b.x + bf.x, 0.f);
        o.y = fmaxf(a.y + b.y + bf.y, 0.f);
        *reinterpret_cast<float2*>(&out[((size_t)(b0 + r) * N_INST + i) * N_FEAT + f]) = o;
    }
}

// ---------------------------------------------------------------------------
extern "C" void kernel_launch(void* const* d_in, const int* in_sizes, int n_in,
                              void* d_out, int out_size) {
    (void)in_sizes; (void)n_in; (void)out_size;
    const float* x    = (const float*)d_in[0];
    const float* mask = (const float*)d_in[1];
    const float* A    = (const float*)d_in[2];
    const float* Bp   = (const float*)d_in[3];
    const float* bfin = (const float*)d_in[4];
    float* out = (float*)d_out;

    cudaFuncSetAttribute(tmsspd_main_kernel,
                         cudaFuncAttributeMaxDynamicSharedMemorySize, SM_TOTAL);

    compute_G_kernel<<<N_INST * NC, 256>>>(A, Bp);

    dim3 grid(B_SZ / 128, N_INST);
    tmsspd_main_kernel<<<grid, NTHR, SM_TOTAL>>>(x, mask, bfin, out);
}